// round 10
// baseline (speedup 1.0000x reference)
#include <cuda_runtime.h>
#include <cuda_bf16.h>

#define TWO_PI_F     6.2831853071795864769f
#define PI_F         3.14159265358979323846f
#define INV_TWO_PI_F 0.15915494309189533577f
#define INV_4PI2_F   0.025330295910584444f   // 1/(4*pi^2)

typedef unsigned long long u64;

// ---------- packed f32x2 primitives (Blackwell) ----------
__device__ __forceinline__ u64 pk2(float lo, float hi) {
    u64 r; asm("mov.b64 %0, {%1,%2};" : "=l"(r) : "f"(lo), "f"(hi)); return r;
}
__device__ __forceinline__ u64 pk2b(float v) {
    u64 r; asm("mov.b64 %0, {%1,%1};" : "=l"(r) : "f"(v)); return r;
}
__device__ __forceinline__ void upk2(u64 v, float& lo, float& hi) {
    asm("mov.b64 {%0,%1}, %2;" : "=f"(lo), "=f"(hi) : "l"(v));
}
__device__ __forceinline__ u64 f2add(u64 a, u64 b) {
    u64 r; asm("add.rn.f32x2 %0,%1,%2;" : "=l"(r) : "l"(a), "l"(b)); return r;
}
__device__ __forceinline__ u64 f2sub(u64 a, u64 b) {
    u64 r; asm("sub.rn.f32x2 %0,%1,%2;" : "=l"(r) : "l"(a), "l"(b)); return r;
}
__device__ __forceinline__ u64 f2mul(u64 a, u64 b) {
    u64 r; asm("mul.rn.f32x2 %0,%1,%2;" : "=l"(r) : "l"(a), "l"(b)); return r;
}
__device__ __forceinline__ u64 f2fma(u64 a, u64 b, u64 c) {
    u64 r; asm("fma.rn.f32x2 %0,%1,%2,%3;" : "=l"(r) : "l"(a), "l"(b), "l"(c)); return r;
}

// ---------- scalar dr (per-area id precompute only) ----------
__device__ __forceinline__ float dr_s(float x) {
    return fmaf(-__sinf(x * TWO_PI_F), INV_TWO_PI_F, x);
}
__device__ __forceinline__ float hdr_s(float x) { return dr_s(dr_s(dr_s(x))); }

// ---------- packed dr in PHASE SPACE: theta' = theta - sin(theta) (MUFU) ----------
__device__ __forceinline__ u64 dr_phase2(u64 ph) {
    float lo, hi; upk2(ph, lo, hi);
    u64 s = pk2(__sinf(lo), __sinf(hi));
    return f2sub(ph, s);
}

// ---------- packed dr, degree-7 economized poly (FMA pipe, x-space) ----------
__device__ __forceinline__ u64 dr_poly7(u64 x) {
    const u64 KMH = pk2b(-0.5f);
    const u64 H3  = pk2b(-9.2444232f);
    const u64 H2  = pk2b( 12.5421093f);
    const u64 H1  = pk2b(-6.5576576f);
    const u64 H0  = pk2b( 0.99981925f);
    u64 u = f2add(x, KMH);
    u64 e = f2mul(u, u);
    u64 p = f2fma(e, H3, H2);
    p = f2fma(p, e, H1);
    p = f2fma(p, e, H0);
    return f2fma(p, u, x);
}
__device__ __forceinline__ u64 hdr_poly7(u64 x) { return dr_poly7(dr_poly7(dr_poly7(x))); }

// ---------- packed dr, degree-7, PHASE-SCALED OUTPUT: phi = 2*pi*dr(x) ----------
__device__ __forceinline__ u64 dr_poly7_phase(u64 x) {
    const u64 KMH = pk2b(-0.5f);
    const u64 B3  = pk2b(-58.08440f);
    const u64 B2  = pk2b( 78.80440f);
    const u64 B1  = pk2b(-41.20490f);
    const u64 B0  = pk2b( 12.565245f);
    const u64 KPI = pk2b(PI_F);
    u64 u = f2add(x, KMH);
    u64 e = f2mul(u, u);
    u64 p = f2fma(e, B3, B2);
    p = f2fma(p, e, B1);
    p = f2fma(p, e, B0);
    return f2fma(p, u, KPI);
}

// ---------- packed dr, degree-9 (final drs, high accuracy, x-space) ----------
__device__ __forceinline__ u64 dr_poly9(u64 x) {
    const u64 KMH = pk2b(-0.5f);
    const u64 G4  = pk2b( 5.2148544f);
    const u64 G3  = pk2b(-11.8518504f);
    const u64 G2  = pk2b( 12.9495198f);
    const u64 G1  = pk2b(-6.5780281f);
    const u64 G0  = pk2b( 0.99997840f);
    u64 u = f2add(x, KMH);
    u64 e = f2mul(u, u);
    u64 p = f2fma(e, G4, G3);
    p = f2fma(p, e, G2);
    p = f2fma(p, e, G1);
    p = f2fma(p, e, G0);
    return f2fma(p, u, x);
}

// 2 warps per area, 4 pixels per thread, 2-stage pipeline over MUFU rounds:
// iteration k runs stage A(pixel k) + stage B(pixel k-1) => 8 live phase chains.
__global__ __launch_bounds__(256, 3)
void deconv_masks_kernel(const float*  __restrict__ img,
                         const float4* __restrict__ mask0,
                         const float4* __restrict__ mask1,
                         const float*  __restrict__ mid,
                         float*        __restrict__ out,
                         int n_pix_total, int n_areas)
{
    __shared__ float4 part[8];

    const int tid   = threadIdx.x;
    const int lane  = tid & 31;
    const int wid   = tid >> 5;
    const int half  = wid & 1;
    const int area  = blockIdx.x * 4 + (wid >> 1);
    if (area >= n_areas) return;

    float h = 0.0f;
    if (lane < 4) h = hdr_s(mid[(size_t)area * 4 + lane]);
    const float h0 = __shfl_sync(0xffffffffu, h, 0);
    const float h1 = __shfl_sync(0xffffffffu, h, 1);
    const float h2 = __shfl_sync(0xffffffffu, h, 2);
    const float h3 = __shfl_sync(0xffffffffu, h, 3);

    // ch 0,1: phase-folded eq consts (phi_t = ah*c1 + c0 = 2pi*t)
    const u64 C1_0 = pk2b(TWO_PI_F*(2.0f*h0 - 1.0f)), C0_0 = pk2b(TWO_PI_F*(1.0f - h0));
    const u64 C1_1 = pk2b(TWO_PI_F*(2.0f*h1 - 1.0f)), C0_1 = pk2b(TWO_PI_F*(1.0f - h1));
    // ch 2,3: x-space eq consts (t = ah*(2h-1) + (1-h))
    const u64 D1_2 = pk2b(2.0f*h2 - 1.0f), D0_2 = pk2b(1.0f - h2);
    const u64 D1_3 = pk2b(2.0f*h3 - 1.0f), D0_3 = pk2b(1.0f - h3);
    const u64 KI4  = pk2b(INV_4PI2_F);

    const size_t base = (size_t)area * 256 + (size_t)half * 128 + lane;

    u64 mv[4];
    float4 acc = make_float4(0.f, 0.f, 0.f, 0.f);

    // ---- prologue: load pixel 0, hdr(a) pixel 0 ----
    float4 v0 = mask0[base];
    float4 v1 = mask1[base];
    float  ivc = img[base];      // iv of pixel k
    float  ivp = 0.0f;           // iv of pixel k-1

    u64 ah0 = hdr_poly7(pk2(v0.x, v1.x));
    u64 ah1 = hdr_poly7(pk2(v0.y, v1.y));
    u64 ah2 = hdr_poly7(pk2(v0.z, v1.z));
    u64 ah3 = hdr_poly7(pk2(v0.w, v1.w));

    u64 p0 = 0, p1 = 0, p2 = 0, p3 = 0;   // pixel k-1 state after stage A

    #pragma unroll
    for (int k = 0; k < 5; k++) {
        // early loads for pixel k+1
        float4 w0, w1; float ivn = 0.0f;
        if (k < 3) {
            const size_t np = base + (size_t)(k + 1) * 32;
            w0 = mask0[np]; w1 = mask1[np]; ivn = img[np];
        }

        u64 f0 = 0, f1 = 0, f2v = 0, f3 = 0;
        if (k < 4) {
            // eq: ch01 -> phase directly; ch23 -> x then poly phase-dr (FMA)
            f0  = f2fma(ah0, C1_0, C0_0);
            f1  = f2fma(ah1, C1_1, C0_1);
            f2v = dr_poly7_phase(f2fma(ah2, D1_2, D0_2));
            f3  = dr_poly7_phase(f2fma(ah3, D1_3, D0_3));
        }

        // ---- interleaved MUFU block: stage A(k) + stage B(k-1), 8 chains ----
        if (k < 4) { f0 = dr_phase2(f0); f1 = dr_phase2(f1); }        // A: ch01 r1
        if (k > 0) { p0 = dr_phase2(p0); p1 = dr_phase2(p1); }        // B: ch01 r3
        if (k < 4) { f2v = dr_phase2(f2v); f3 = dr_phase2(f3); }      // A: ch23 r2
        if (k > 0) { p2 = dr_phase2(p2); p3 = dr_phase2(p3); }        // B: ch23 r3
        if (k < 4) { f0 = dr_phase2(f0); f1 = dr_phase2(f1); }        // A: ch01 r2
        if (k > 0) { p0 = dr_phase2(p0); p1 = dr_phase2(p1); }        // B: ch01 r4
        if (k > 0) { p2 = dr_phase2(p2); p3 = dr_phase2(p3); }        // B: ch23 r4

        // ---- finish pixel k-1 (FMA) ----
        if (k > 0) {
            u64 pa = f2mul(f2mul(p0, p1), KI4);
            u64 pb = f2mul(f2mul(p2, p3), KI4);
            u64 mm = f2mul(dr_poly9(pa), dr_poly9(pb));
            mv[k - 1] = mm;
            float m0, m1; upk2(mm, m0, m1);
            acc.x = fmaf(m0, ivp, acc.x);
            acc.y += m0;
            acc.z = fmaf(m1, ivp, acc.z);
            acc.w += m1;
        }

        // ---- hdr(a) for pixel k+1 (FMA, fills MUFU latency) ----
        if (k < 3) {
            ah0 = hdr_poly7(pk2(w0.x, w1.x));
            ah1 = hdr_poly7(pk2(w0.y, w1.y));
            ah2 = hdr_poly7(pk2(w0.z, w1.z));
            ah3 = hdr_poly7(pk2(w0.w, w1.w));
        }

        // rotate pipeline
        if (k < 4) { p0 = f0; p1 = f1; p2 = f2v; p3 = f3; ivp = ivc; ivc = ivn; }
    }

    // warp-wide butterfly
    #pragma unroll
    for (int off = 16; off > 0; off >>= 1) {
        acc.x += __shfl_xor_sync(0xffffffffu, acc.x, off);
        acc.y += __shfl_xor_sync(0xffffffffu, acc.y, off);
        acc.z += __shfl_xor_sync(0xffffffffu, acc.z, off);
        acc.w += __shfl_xor_sync(0xffffffffu, acc.w, off);
    }

    if (lane == 0) part[wid] = acc;
    __syncthreads();
    const float4 o = part[wid ^ 1];

    const float mean0 = __fdividef(acc.x + o.x, acc.y + o.y);
    const float mean1 = __fdividef(acc.z + o.z, acc.w + o.w);
    const u64 KMEAN = pk2(mean0, mean1);

    #pragma unroll
    for (int k = 0; k < 4; k++) {
        const size_t pix = base + (size_t)k * 32;
        u64 ow = f2mul(mv[k], KMEAN);
        float o0, o1; upk2(ow, o0, o1);
        out[pix]                       = o0;
        out[pix + (size_t)n_pix_total] = o1;
    }
}

extern "C" void kernel_launch(void* const* d_in, const int* in_sizes, int n_in,
                              void* d_out, int out_size) {
    const float*  img   = (const float*) d_in[0];
    const float4* mask0 = (const float4*)d_in[1];
    const float4* mask1 = (const float4*)d_in[2];
    const float*  mid   = (const float*) d_in[3];
    float*        out   = (float*)d_out;

    const int n_pix  = in_sizes[0];
    const int areas  = n_pix / 256;
    const int blocks = (areas + 3) / 4;

    deconv_masks_kernel<<<blocks, 256>>>(img, mask0, mask1, mid, out, n_pix, areas);
}

// round 11
// speedup vs baseline: 1.0506x; 1.0506x over previous
#include <cuda_runtime.h>
#include <cuda_bf16.h>

#define TWO_PI_F     6.2831853071795864769f
#define PI_F         3.14159265358979323846f
#define INV_TWO_PI_F 0.15915494309189533577f
#define INV_4PI2_F   0.025330295910584444f   // 1/(4*pi^2)

typedef unsigned long long u64;

// ---------- packed f32x2 primitives (Blackwell) ----------
__device__ __forceinline__ u64 pk2(float lo, float hi) {
    u64 r; asm("mov.b64 %0, {%1,%2};" : "=l"(r) : "f"(lo), "f"(hi)); return r;
}
__device__ __forceinline__ u64 pk2b(float v) {
    u64 r; asm("mov.b64 %0, {%1,%1};" : "=l"(r) : "f"(v)); return r;
}
__device__ __forceinline__ void upk2(u64 v, float& lo, float& hi) {
    asm("mov.b64 {%0,%1}, %2;" : "=f"(lo), "=f"(hi) : "l"(v));
}
__device__ __forceinline__ u64 f2add(u64 a, u64 b) {
    u64 r; asm("add.rn.f32x2 %0,%1,%2;" : "=l"(r) : "l"(a), "l"(b)); return r;
}
__device__ __forceinline__ u64 f2sub(u64 a, u64 b) {
    u64 r; asm("sub.rn.f32x2 %0,%1,%2;" : "=l"(r) : "l"(a), "l"(b)); return r;
}
__device__ __forceinline__ u64 f2mul(u64 a, u64 b) {
    u64 r; asm("mul.rn.f32x2 %0,%1,%2;" : "=l"(r) : "l"(a), "l"(b)); return r;
}
__device__ __forceinline__ u64 f2fma(u64 a, u64 b, u64 c) {
    u64 r; asm("fma.rn.f32x2 %0,%1,%2,%3;" : "=l"(r) : "l"(a), "l"(b), "l"(c)); return r;
}

// ---------- scalar dr (per-area id precompute only) ----------
__device__ __forceinline__ float dr_s(float x) {
    return fmaf(-__sinf(x * TWO_PI_F), INV_TWO_PI_F, x);
}
__device__ __forceinline__ float hdr_s(float x) { return dr_s(dr_s(dr_s(x))); }

// ---------- packed dr in PHASE SPACE: phi' = phi - sin(phi) (MUFU) ----------
__device__ __forceinline__ u64 dr_phase2(u64 ph) {
    float lo, hi; upk2(ph, lo, hi);
    u64 s = pk2(__sinf(lo), __sinf(hi));
    return f2sub(ph, s);
}

// ---------- v-space dr, degree-7: v' = v * Htilde(v^2), Htilde = 1 + H ----------
// dr(x)-0.5 = (x-0.5)*(1 + H((x-0.5)^2)); verified deg-7 H coefficients.
// 5 packed ops per dr (vs 6 in x-space).
__device__ __forceinline__ u64 dr_v7(u64 v) {
    const u64 H3  = pk2b(-9.2444232f);
    const u64 H2  = pk2b( 12.5421093f);
    const u64 H1  = pk2b(-6.5576576f);
    const u64 HT0 = pk2b( 1.99981925f);   // 1 + H0
    u64 e = f2mul(v, v);
    u64 p = f2fma(e, H3, H2);
    p = f2fma(p, e, H1);
    p = f2fma(p, e, HT0);
    return f2mul(p, v);
}
__device__ __forceinline__ u64 hdr_v7(u64 v) { return dr_v7(dr_v7(dr_v7(v))); }

// ---------- v-space dr with PHASE output: phi = 2*pi*dr(t), input v_t = t-0.5 ----------
// phi = pi + v_t * (2*pi*(1+H(v_t^2))). 5 packed ops.
__device__ __forceinline__ u64 dr_v7_phase(u64 v) {
    const u64 B3  = pk2b(-58.0845070f);   // 2*pi*H3
    const u64 B2  = pk2b( 78.8044230f);   // 2*pi*H2
    const u64 B1  = pk2b(-41.2050600f);   // 2*pi*H1
    const u64 B0  = pk2b( 12.5652349f);   // 2*pi*(1+H0)
    const u64 KPI = pk2b(PI_F);
    u64 e = f2mul(v, v);
    u64 p = f2fma(e, B3, B2);
    p = f2fma(p, e, B1);
    p = f2fma(p, e, B0);
    return f2fma(p, v, KPI);
}

// ---------- x-space dr, degree-7 (final drs; 6 packed ops) ----------
__device__ __forceinline__ u64 dr_poly7(u64 x) {
    const u64 KMH = pk2b(-0.5f);
    const u64 H3  = pk2b(-9.2444232f);
    const u64 H2  = pk2b( 12.5421093f);
    const u64 H1  = pk2b(-6.5576576f);
    const u64 H0  = pk2b( 0.99981925f);
    u64 u = f2add(x, KMH);
    u64 e = f2mul(u, u);
    u64 p = f2fma(e, H3, H2);
    p = f2fma(p, e, H1);
    p = f2fma(p, e, H0);
    return f2fma(p, u, x);
}

// 2 warps per area, 4 pixels per thread.
__global__ __launch_bounds__(256, 3)
void deconv_masks_kernel(const float*  __restrict__ img,
                         const float4* __restrict__ mask0,
                         const float4* __restrict__ mask1,
                         const float*  __restrict__ mid,
                         float*        __restrict__ out,
                         int n_pix_total, int n_areas)
{
    __shared__ float4 part[8];

    const int tid   = threadIdx.x;
    const int lane  = tid & 31;
    const int wid   = tid >> 5;
    const int half  = wid & 1;
    const int area  = blockIdx.x * 4 + (wid >> 1);
    if (area >= n_areas) return;

    float h = 0.0f;
    if (lane < 4) h = hdr_s(mid[(size_t)area * 4 + lane]);
    const float h0 = __shfl_sync(0xffffffffu, h, 0);
    const float h1 = __shfl_sync(0xffffffffu, h, 1);
    const float h2 = __shfl_sync(0xffffffffu, h, 2);
    const float h3 = __shfl_sync(0xffffffffu, h, 3);

    // ch 0,1: phase entry  phi_t = v_ah * 2pi(2h-1) + pi
    const u64 C1_0 = pk2b(TWO_PI_F*(2.0f*h0 - 1.0f));
    const u64 C1_1 = pk2b(TWO_PI_F*(2.0f*h1 - 1.0f));
    const u64 KPI  = pk2b(PI_F);
    // ch 2,3: v entry  v_t = v_ah * (2h-1)
    const u64 D1_2 = pk2b(2.0f*h2 - 1.0f);
    const u64 D1_3 = pk2b(2.0f*h3 - 1.0f);
    const u64 KI4  = pk2b(INV_4PI2_F);
    const u64 KMH  = pk2b(-0.5f);

    const size_t base = (size_t)area * 256 + (size_t)half * 128 + lane;

    u64 mv[4];
    float4 acc = make_float4(0.f, 0.f, 0.f, 0.f);

    // prefetch pixel 0
    float4 v0 = mask0[base];
    float4 v1 = mask1[base];
    float  iv = img[base];

    #pragma unroll
    for (int k = 0; k < 4; k++) {
        // issue next pixel's loads early
        float4 w0, w1; float niv = 0.0f;
        if (k < 3) {
            const size_t np = base + (size_t)(k + 1) * 32;
            w0 = mask0[np]; w1 = mask1[np]; niv = img[np];
        }

        // hdr(a) in v-space (FMA)
        u64 vh0 = hdr_v7(f2add(pk2(v0.x, v1.x), KMH));
        u64 vh1 = hdr_v7(f2add(pk2(v0.y, v1.y), KMH));
        u64 vh2 = hdr_v7(f2add(pk2(v0.z, v1.z), KMH));
        u64 vh3 = hdr_v7(f2add(pk2(v0.w, v1.w), KMH));

        // ch 0,1: phase entry, then 4 MUFU phase-drs
        u64 f0 = f2fma(vh0, C1_0, KPI);
        u64 f1 = f2fma(vh1, C1_1, KPI);
        // ch 2,3: v entry, poly phase-dr (FMA), then 3 MUFU phase-drs
        u64 f2v = dr_v7_phase(f2mul(vh2, D1_2));
        u64 f3  = dr_v7_phase(f2mul(vh3, D1_3));

        f0 = dr_phase2(f0); f1 = dr_phase2(f1);            // ch01 round 1
        f0 = dr_phase2(f0); f1 = dr_phase2(f1);            // ch01 round 2
        f2v = dr_phase2(f2v); f3 = dr_phase2(f3);          // ch23 round 2
        f0 = dr_phase2(f0); f1 = dr_phase2(f1);            // ch01 round 3
        f2v = dr_phase2(f2v); f3 = dr_phase2(f3);          // ch23 round 3
        f0 = dr_phase2(f0); f1 = dr_phase2(f1);            // ch01 round 4
        f2v = dr_phase2(f2v); f3 = dr_phase2(f3);          // ch23 round 4

        // back to x-space; final drs (deg-7, FMA)
        u64 pa = f2mul(f2mul(f0, f1), KI4);
        u64 pb = f2mul(f2mul(f2v, f3), KI4);
        u64 mm = f2mul(dr_poly7(pa), dr_poly7(pb));

        mv[k] = mm;
        float m0, m1; upk2(mm, m0, m1);
        acc.x = fmaf(m0, iv, acc.x);
        acc.y += m0;
        acc.z = fmaf(m1, iv, acc.z);
        acc.w += m1;

        v0 = w0; v1 = w1; iv = niv;
    }

    // warp-wide butterfly
    #pragma unroll
    for (int off = 16; off > 0; off >>= 1) {
        acc.x += __shfl_xor_sync(0xffffffffu, acc.x, off);
        acc.y += __shfl_xor_sync(0xffffffffu, acc.y, off);
        acc.z += __shfl_xor_sync(0xffffffffu, acc.z, off);
        acc.w += __shfl_xor_sync(0xffffffffu, acc.w, off);
    }

    if (lane == 0) part[wid] = acc;
    __syncthreads();
    const float4 o = part[wid ^ 1];

    const float mean0 = __fdividef(acc.x + o.x, acc.y + o.y);
    const float mean1 = __fdividef(acc.z + o.z, acc.w + o.w);
    const u64 KMEAN = pk2(mean0, mean1);

    #pragma unroll
    for (int k = 0; k < 4; k++) {
        const size_t pix = base + (size_t)k * 32;
        u64 ow = f2mul(mv[k], KMEAN);
        float o0, o1; upk2(ow, o0, o1);
        out[pix]                       = o0;
        out[pix + (size_t)n_pix_total] = o1;
    }
}

extern "C" void kernel_launch(void* const* d_in, const int* in_sizes, int n_in,
                              void* d_out, int out_size) {
    const float*  img   = (const float*) d_in[0];
    const float4* mask0 = (const float4*)d_in[1];
    const float4* mask1 = (const float4*)d_in[2];
    const float*  mid   = (const float*) d_in[3];
    float*        out   = (float*)d_out;

    const int n_pix  = in_sizes[0];
    const int areas  = n_pix / 256;
    const int blocks = (areas + 3) / 4;

    deconv_masks_kernel<<<blocks, 256>>>(img, mask0, mask1, mid, out, n_pix, areas);
}

// round 12
// speedup vs baseline: 1.0655x; 1.0142x over previous
#include <cuda_runtime.h>
#include <cuda_bf16.h>

#define TWO_PI_F     6.2831853071795864769f
#define PI_F         3.14159265358979323846f
#define INV_TWO_PI_F 0.15915494309189533577f
#define INV_4PI2_F   0.025330295910584444f   // 1/(4*pi^2)

typedef unsigned long long u64;

// ---------- packed f32x2 primitives (Blackwell) ----------
__device__ __forceinline__ u64 pk2(float lo, float hi) {
    u64 r; asm("mov.b64 %0, {%1,%2};" : "=l"(r) : "f"(lo), "f"(hi)); return r;
}
__device__ __forceinline__ u64 pk2b(float v) {
    u64 r; asm("mov.b64 %0, {%1,%1};" : "=l"(r) : "f"(v)); return r;
}
__device__ __forceinline__ void upk2(u64 v, float& lo, float& hi) {
    asm("mov.b64 {%0,%1}, %2;" : "=f"(lo), "=f"(hi) : "l"(v));
}
__device__ __forceinline__ u64 f2add(u64 a, u64 b) {
    u64 r; asm("add.rn.f32x2 %0,%1,%2;" : "=l"(r) : "l"(a), "l"(b)); return r;
}
__device__ __forceinline__ u64 f2sub(u64 a, u64 b) {
    u64 r; asm("sub.rn.f32x2 %0,%1,%2;" : "=l"(r) : "l"(a), "l"(b)); return r;
}
__device__ __forceinline__ u64 f2mul(u64 a, u64 b) {
    u64 r; asm("mul.rn.f32x2 %0,%1,%2;" : "=l"(r) : "l"(a), "l"(b)); return r;
}
__device__ __forceinline__ u64 f2fma(u64 a, u64 b, u64 c) {
    u64 r; asm("fma.rn.f32x2 %0,%1,%2,%3;" : "=l"(r) : "l"(a), "l"(b), "l"(c)); return r;
}

// ---------- scalar dr (per-area id precompute only) ----------
__device__ __forceinline__ float dr_s(float x) {
    return fmaf(-__sinf(x * TWO_PI_F), INV_TWO_PI_F, x);
}
__device__ __forceinline__ float hdr_s(float x) { return dr_s(dr_s(dr_s(x))); }

// ---------- packed dr in PHASE SPACE: phi' = phi - sin(phi) (MUFU) ----------
__device__ __forceinline__ u64 dr_phase2(u64 ph) {
    float lo, hi; upk2(ph, lo, hi);
    u64 s = pk2(__sinf(lo), __sinf(hi));
    return f2sub(ph, s);
}

// ---------- v-space dr, degree-7: v' = v * Htilde(v^2), Htilde = 1 + H ----------
__device__ __forceinline__ u64 dr_v7(u64 v) {
    const u64 H3  = pk2b(-9.2444232f);
    const u64 H2  = pk2b( 12.5421093f);
    const u64 H1  = pk2b(-6.5576576f);
    const u64 HT0 = pk2b( 1.99981925f);   // 1 + H0
    u64 e = f2mul(v, v);
    u64 p = f2fma(e, H3, H2);
    p = f2fma(p, e, H1);
    p = f2fma(p, e, HT0);
    return f2mul(p, v);
}
__device__ __forceinline__ u64 hdr_v7(u64 v) { return dr_v7(dr_v7(dr_v7(v))); }

// ---------- v-space dr with PHASE output: phi = 2*pi*dr(t), input v_t = t-0.5 ----------
__device__ __forceinline__ u64 dr_v7_phase(u64 v) {
    const u64 B3  = pk2b(-58.0845070f);   // 2*pi*H3
    const u64 B2  = pk2b( 78.8044230f);   // 2*pi*H2
    const u64 B1  = pk2b(-41.2050600f);   // 2*pi*H1
    const u64 B0  = pk2b( 12.5652349f);   // 2*pi*(1+H0)
    const u64 KPI = pk2b(PI_F);
    u64 e = f2mul(v, v);
    u64 p = f2fma(e, B3, B2);
    p = f2fma(p, e, B1);
    p = f2fma(p, e, B0);
    return f2fma(p, v, KPI);
}

// ---------- x-space dr, degree-7 (final drs) ----------
__device__ __forceinline__ u64 dr_poly7(u64 x) {
    const u64 KMH = pk2b(-0.5f);
    const u64 H3  = pk2b(-9.2444232f);
    const u64 H2  = pk2b( 12.5421093f);
    const u64 H1  = pk2b(-6.5576576f);
    const u64 H0  = pk2b( 0.99981925f);
    u64 u = f2add(x, KMH);
    u64 e = f2mul(u, u);
    u64 p = f2fma(e, H3, H2);
    p = f2fma(p, e, H1);
    p = f2fma(p, e, H0);
    return f2fma(p, u, x);
}

// 2 warps per area, 4 pixels per thread. All 4 channels uniform:
// v-space hdr(a), v entry mul, poly phase-dr, 3 MUFU phase-drs.
__global__ __launch_bounds__(256, 3)
void deconv_masks_kernel(const float*  __restrict__ img,
                         const float4* __restrict__ mask0,
                         const float4* __restrict__ mask1,
                         const float*  __restrict__ mid,
                         float*        __restrict__ out,
                         int n_pix_total, int n_areas)
{
    __shared__ float4 part[8];

    const int tid   = threadIdx.x;
    const int lane  = tid & 31;
    const int wid   = tid >> 5;
    const int half  = wid & 1;
    const int area  = blockIdx.x * 4 + (wid >> 1);
    if (area >= n_areas) return;

    float h = 0.0f;
    if (lane < 4) h = hdr_s(mid[(size_t)area * 4 + lane]);
    const float h0 = __shfl_sync(0xffffffffu, h, 0);
    const float h1 = __shfl_sync(0xffffffffu, h, 1);
    const float h2 = __shfl_sync(0xffffffffu, h, 2);
    const float h3 = __shfl_sync(0xffffffffu, h, 3);

    // v entry: v_t = v_ah * (2h-1)   (then poly phase-dr)
    const u64 D1_0 = pk2b(2.0f*h0 - 1.0f);
    const u64 D1_1 = pk2b(2.0f*h1 - 1.0f);
    const u64 D1_2 = pk2b(2.0f*h2 - 1.0f);
    const u64 D1_3 = pk2b(2.0f*h3 - 1.0f);
    const u64 KI4  = pk2b(INV_4PI2_F);
    const u64 KMH  = pk2b(-0.5f);

    const size_t base = (size_t)area * 256 + (size_t)half * 128 + lane;

    u64 mv[4];
    u64 accN = 0, accD = 0;    // packed (num0,num1), (den0,den1)

    // prefetch pixel 0
    float4 v0 = mask0[base];
    float4 v1 = mask1[base];
    float  iv = img[base];

    #pragma unroll
    for (int k = 0; k < 4; k++) {
        // issue next pixel's loads early
        float4 w0, w1; float niv = 0.0f;
        if (k < 3) {
            const size_t np = base + (size_t)(k + 1) * 32;
            w0 = mask0[np]; w1 = mask1[np]; niv = img[np];
        }

        // hdr(a) in v-space (FMA)
        u64 vh0 = hdr_v7(f2add(pk2(v0.x, v1.x), KMH));
        u64 vh1 = hdr_v7(f2add(pk2(v0.y, v1.y), KMH));
        u64 vh2 = hdr_v7(f2add(pk2(v0.z, v1.z), KMH));
        u64 vh3 = hdr_v7(f2add(pk2(v0.w, v1.w), KMH));

        // all channels: v entry, poly phase-dr (FMA), then 3 MUFU phase-drs
        u64 f0  = dr_v7_phase(f2mul(vh0, D1_0));
        u64 f1  = dr_v7_phase(f2mul(vh1, D1_1));
        u64 f2v = dr_v7_phase(f2mul(vh2, D1_2));
        u64 f3  = dr_v7_phase(f2mul(vh3, D1_3));

        f0 = dr_phase2(f0); f1 = dr_phase2(f1);            // round 2
        f2v = dr_phase2(f2v); f3 = dr_phase2(f3);
        f0 = dr_phase2(f0); f1 = dr_phase2(f1);            // round 3
        f2v = dr_phase2(f2v); f3 = dr_phase2(f3);
        f0 = dr_phase2(f0); f1 = dr_phase2(f1);            // round 4
        f2v = dr_phase2(f2v); f3 = dr_phase2(f3);

        // back to x-space; final drs (deg-7, FMA)
        u64 pa = f2mul(f2mul(f0, f1), KI4);
        u64 pb = f2mul(f2mul(f2v, f3), KI4);
        u64 mm = f2mul(dr_poly7(pa), dr_poly7(pb));

        mv[k] = mm;
        accN = f2fma(mm, pk2b(iv), accN);
        accD = f2add(accD, mm);

        v0 = w0; v1 = w1; iv = niv;
    }

    // unpack packed accumulators, butterfly over the warp
    float4 acc;
    upk2(accN, acc.x, acc.z);   // (num0, num1)
    upk2(accD, acc.y, acc.w);   // (den0, den1)

    #pragma unroll
    for (int off = 16; off > 0; off >>= 1) {
        acc.x += __shfl_xor_sync(0xffffffffu, acc.x, off);
        acc.y += __shfl_xor_sync(0xffffffffu, acc.y, off);
        acc.z += __shfl_xor_sync(0xffffffffu, acc.z, off);
        acc.w += __shfl_xor_sync(0xffffffffu, acc.w, off);
    }

    if (lane == 0) part[wid] = acc;
    __syncthreads();
    const float4 o = part[wid ^ 1];

    const float mean0 = __fdividef(acc.x + o.x, acc.y + o.y);
    const float mean1 = __fdividef(acc.z + o.z, acc.w + o.w);
    const u64 KMEAN = pk2(mean0, mean1);

    #pragma unroll
    for (int k = 0; k < 4; k++) {
        const size_t pix = base + (size_t)k * 32;
        u64 ow = f2mul(mv[k], KMEAN);
        float o0, o1; upk2(ow, o0, o1);
        out[pix]                       = o0;
        out[pix + (size_t)n_pix_total] = o1;
    }
}

extern "C" void kernel_launch(void* const* d_in, const int* in_sizes, int n_in,
                              void* d_out, int out_size) {
    const float*  img   = (const float*) d_in[0];
    const float4* mask0 = (const float4*)d_in[1];
    const float4* mask1 = (const float4*)d_in[2];
    const float*  mid   = (const float*) d_in[3];
    float*        out   = (float*)d_out;

    const int n_pix  = in_sizes[0];
    const int areas  = n_pix / 256;
    const int blocks = (areas + 3) / 4;

    deconv_masks_kernel<<<blocks, 256>>>(img, mask0, mask1, mid, out, n_pix, areas);
}